// round 1
// baseline (speedup 1.0000x reference)
#include <cuda_runtime.h>
#include <math.h>

#define HEADS 8
#define HW 64
#define D 32
#define NTOK 4096
#define DIMX 256
#define INCDIM 768

// ---------------- scratch (static device globals; no allocation) -------------
__device__ float g_Q[HEADS * NTOK * D];            // 4 MB  (h, n, e) elu(q)+1+eps
__device__ float g_K[HEADS * NTOK * D];            // 4 MB
__device__ float g_V[HEADS * NTOK * D];            // 4 MB
__device__ float g_U[(size_t)HEADS * HW * HW * D * D]; // 134 MB row-cumsum of k (x) v
__device__ float g_Kc[HEADS * HW * HW * D];        // 4 MB row-cumsum of k
__device__ float g_Cat[(size_t)NTOK * INCDIM];     // 12.6 MB concat of window outputs

// ---------------- Kernel 1: fused QKV GEMM + ELU epilogue --------------------
// C[4096 x 768] = x[4096 x 256] @ [wq|wk|wv]; 64x64 tiles, 256 thr, 4x4/thread
__global__ __launch_bounds__(256) void k_qkv(const float* __restrict__ x,
                                             const float* __restrict__ wq,
                                             const float* __restrict__ wk,
                                             const float* __restrict__ wv) {
    __shared__ float As[64 * 16];   // [m][kk]
    __shared__ float Bs[16 * 64];   // [kk][n]
    const int row0 = blockIdx.x * 64;
    const int col0 = blockIdx.y * 64;        // 0..767
    const int part = col0 >> 8;              // 0=q 1=k 2=v
    const int wc0  = col0 & 255;
    const float* W = (part == 0) ? wq : (part == 1) ? wk : wv;
    const int tid = threadIdx.x;
    const int tx = tid & 15, ty = tid >> 4;

    float acc[4][4] = {};
    for (int k0 = 0; k0 < DIMX; k0 += 16) {
#pragma unroll
        for (int i = 0; i < 4; i++) {
            int l = tid + i * 256;
            int m = l >> 4, kk = l & 15;
            As[l] = x[(row0 + m) * DIMX + k0 + kk];
        }
#pragma unroll
        for (int i = 0; i < 4; i++) {
            int l = tid + i * 256;
            int kk = l >> 6, n = l & 63;
            Bs[l] = W[(k0 + kk) * DIMX + wc0 + n];
        }
        __syncthreads();
#pragma unroll
        for (int kk = 0; kk < 16; kk++) {
            float a0 = As[(ty * 4 + 0) * 16 + kk];
            float a1 = As[(ty * 4 + 1) * 16 + kk];
            float a2 = As[(ty * 4 + 2) * 16 + kk];
            float a3 = As[(ty * 4 + 3) * 16 + kk];
            float4 b = *(const float4*)&Bs[kk * 64 + tx * 4];
            acc[0][0] += a0 * b.x; acc[0][1] += a0 * b.y; acc[0][2] += a0 * b.z; acc[0][3] += a0 * b.w;
            acc[1][0] += a1 * b.x; acc[1][1] += a1 * b.y; acc[1][2] += a1 * b.z; acc[1][3] += a1 * b.w;
            acc[2][0] += a2 * b.x; acc[2][1] += a2 * b.y; acc[2][2] += a2 * b.z; acc[2][3] += a2 * b.w;
            acc[3][0] += a3 * b.x; acc[3][1] += a3 * b.y; acc[3][2] += a3 * b.z; acc[3][3] += a3 * b.w;
        }
        __syncthreads();
    }
    float* dst = (part == 0) ? g_Q : (part == 1) ? g_K : g_V;
#pragma unroll
    for (int i = 0; i < 4; i++) {
        int n = row0 + ty * 4 + i;
#pragma unroll
        for (int jv = 0; jv < 4; jv++) {
            int cc = wc0 + tx * 4 + jv;      // column within part
            int h = cc >> 5, e = cc & 31;
            float val = acc[i][jv];
            if (part < 2)
                val = (val > 0.f) ? (val + 1.000001f) : (expf(val) + 1e-6f);
            dst[((size_t)(h * NTOK + n)) * D + e] = val;
        }
    }
}

// ---------------- Kernel 2: row-direction cumsums ----------------------------
// For each (head, col j): U[i] = sum_{i'<=i} k(i',j) (x) v(i',j)   (32x32)
//                         Kc[i] = sum_{i'<=i} k(i',j)              (32)
__global__ __launch_bounds__(256) void k_integral() {
    const int j = blockIdx.x;
    const int h = blockIdx.y;
    __shared__ float ksh[HW * D];
    __shared__ float vsh[HW * D];
    const int tid = threadIdx.x;
#pragma unroll
    for (int r = 0; r < 8; r++) {
        int l = tid + r * 256;
        int i = l >> 5, a = l & 31;
        size_t gi = ((size_t)(h * NTOK + i * HW + j)) * D + a;
        ksh[l] = g_K[gi];
        vsh[l] = g_V[gi];
    }
    __syncthreads();
    const int a = tid >> 3;            // row of the 32x32, 0..31
    const int b = (tid & 7) * 4;       // col group
    float4 acc = make_float4(0.f, 0.f, 0.f, 0.f);
    float kacc = 0.f;
    for (int i = 0; i < HW; i++) {
        float kv = ksh[i * D + a];
        float4 vv = *(const float4*)&vsh[i * D + b];
        acc.x += kv * vv.x; acc.y += kv * vv.y; acc.z += kv * vv.z; acc.w += kv * vv.w;
        *(float4*)&g_U[(((size_t)(h * HW + i)) * HW + j) * (D * D) + tid * 4] = acc;
        if (tid < 32) {
            kacc += ksh[i * D + tid];
            g_Kc[((h * HW + i) * HW + j) * D + tid] = kacc;
        }
    }
}

// ---------------- Kernel 3: windowed linear attention sweep ------------------
// block = (ii, window, head). Sweep j, keep P = running column-prefix of the
// row-band matrix in SMEM; evaluate q^T P at the (<=2 per pixel) event points.
__global__ __launch_bounds__(256) void k_attn() {
    const int ii = blockIdx.x;
    const int win = blockIdx.y;
    const int h = blockIdx.z;
    const int r = (win == 0) ? 32 : (win == 1) ? 16 : 8;   // wh//2

    __shared__ float qsh[HW * D];     // 8 KB
    __shared__ float Msh[D * D];      // 4 KB  running prefix matrix P
    __shared__ float numsh[HW * D];   // 8 KB
    __shared__ float densh[HW];
    __shared__ float pksh[D];         // running prefix of k-band

    const int tid = threadIdx.x;
    const int warp = tid >> 5, lane = tid & 31;

#pragma unroll
    for (int rr = 0; rr < 8; rr++) {
        int l = tid + rr * 256;
        qsh[l] = g_Q[((size_t)(h * NTOK + ii * HW)) * D + l];
        numsh[l] = 0.f;
    }
    *(float4*)&Msh[tid * 4] = make_float4(0.f, 0.f, 0.f, 0.f);
    if (tid < 64) densh[tid] = 0.f;
    if (tid < 32) pksh[tid] = 0.f;

    const int x1 = max(ii - r, 0);
    const int x2 = min(ii + r, HW - 1);
    const int xl = x1 - 1;
    const bool hasl = (xl >= 0);
    const float* Uh = g_U + ((size_t)(h * HW + x2)) * HW * (D * D);
    const float* Ul = hasl ? g_U + ((size_t)(h * HW + xl)) * HW * (D * D) : Uh;
    const float* Kh = g_Kc + (h * HW + x2) * HW * D;
    const float* Kl = hasl ? g_Kc + (h * HW + xl) * HW * D : Kh;

    __syncthreads();

    for (int j = 0; j < HW; j++) {
        // issue global loads before the barrier (overlaps prior-step evals)
        float4 d = *(const float4*)&Uh[(size_t)j * (D * D) + tid * 4];
        float kd = (tid < 32) ? Kh[j * D + tid] : 0.f;
        if (hasl) {
            float4 dl = *(const float4*)&Ul[(size_t)j * (D * D) + tid * 4];
            d.x -= dl.x; d.y -= dl.y; d.z -= dl.z; d.w -= dl.w;
            if (tid < 32) kd -= Kl[j * D + tid];
        }
        __syncthreads();   // previous-step evals finished reading Msh/pksh
        float4 m = *(float4*)&Msh[tid * 4];
        m.x += d.x; m.y += d.y; m.z += d.z; m.w += d.w;
        *(float4*)&Msh[tid * 4] = m;
        if (tid < 32) pksh[tid] += kd;
        __syncthreads();   // P(y=j) ready

        // events: +1 at y2(jj)==j ; -1 at y1(jj)-1==j
        const int nplus = (j == HW - 1) ? (r + 1) : ((j >= r) ? 1 : 0);
        const int jjp0  = (j == HW - 1) ? (HW - 1 - r) : (j - r);
        const int hasminus = (j + r + 1 <= HW - 1) ? 1 : 0;
        const int nev = nplus + hasminus;
        for (int e = warp; e < nev; e += 8) {
            int jj; float sgn;
            if (e < nplus) { jj = jjp0 + e; sgn = 1.f; }
            else           { jj = j + r + 1; sgn = -1.f; }
            const float* qrow = &qsh[jj * D];
            float rv = 0.f;
#pragma unroll
            for (int a = 0; a < 32; a++) rv += qrow[a] * Msh[a * 32 + lane];
            numsh[jj * D + lane] += sgn * rv;
            float p = qrow[lane] * pksh[lane];
#pragma unroll
            for (int off = 16; off; off >>= 1) p += __shfl_xor_sync(0xffffffffu, p, off);
            if (lane == 0) densh[jj] += sgn * p;
        }
    }
    __syncthreads();
#pragma unroll
    for (int rr = 0; rr < 8; rr++) {
        int l = tid + rr * 256;
        int jj = l >> 5, e = l & 31;
        float o = numsh[l] / (densh[jj] + 1e-6f);
        g_Cat[(size_t)(ii * HW + jj) * INCDIM + win * DIMX + h * D + e] = o;
    }
}

// ---------------- Kernel 4: output GEMM + bias -------------------------------
// out[4096 x 256] = Cat[4096 x 768] @ wo[768 x 256] + bo
__global__ __launch_bounds__(256) void k_out(const float* __restrict__ wo,
                                             const float* __restrict__ bo,
                                             float* __restrict__ out) {
    __shared__ float As[64 * 16];
    __shared__ float Bs[16 * 64];
    const int row0 = blockIdx.x * 64;
    const int col0 = blockIdx.y * 64;    // 0..255
    const int tid = threadIdx.x;
    const int tx = tid & 15, ty = tid >> 4;

    float acc[4][4] = {};
    for (int k0 = 0; k0 < INCDIM; k0 += 16) {
#pragma unroll
        for (int i = 0; i < 4; i++) {
            int l = tid + i * 256;
            int m = l >> 4, kk = l & 15;
            As[l] = g_Cat[(size_t)(row0 + m) * INCDIM + k0 + kk];
        }
#pragma unroll
        for (int i = 0; i < 4; i++) {
            int l = tid + i * 256;
            int kk = l >> 6, n = l & 63;
            Bs[l] = wo[(k0 + kk) * DIMX + col0 + n];
        }
        __syncthreads();
#pragma unroll
        for (int kk = 0; kk < 16; kk++) {
            float a0 = As[(ty * 4 + 0) * 16 + kk];
            float a1 = As[(ty * 4 + 1) * 16 + kk];
            float a2 = As[(ty * 4 + 2) * 16 + kk];
            float a3 = As[(ty * 4 + 3) * 16 + kk];
            float4 b = *(const float4*)&Bs[kk * 64 + tx * 4];
            acc[0][0] += a0 * b.x; acc[0][1] += a0 * b.y; acc[0][2] += a0 * b.z; acc[0][3] += a0 * b.w;
            acc[1][0] += a1 * b.x; acc[1][1] += a1 * b.y; acc[1][2] += a1 * b.z; acc[1][3] += a1 * b.w;
            acc[2][0] += a2 * b.x; acc[2][1] += a2 * b.y; acc[2][2] += a2 * b.z; acc[2][3] += a2 * b.w;
            acc[3][0] += a3 * b.x; acc[3][1] += a3 * b.y; acc[3][2] += a3 * b.z; acc[3][3] += a3 * b.w;
        }
        __syncthreads();
    }
#pragma unroll
    for (int i = 0; i < 4; i++) {
        int n = row0 + ty * 4 + i;
#pragma unroll
        for (int jv = 0; jv < 4; jv++) {
            int c = col0 + tx * 4 + jv;
            out[(size_t)n * DIMX + c] = acc[i][jv] + bo[c];
        }
    }
}

// ---------------- launch -----------------------------------------------------
extern "C" void kernel_launch(void* const* d_in, const int* in_sizes, int n_in,
                              void* d_out, int out_size) {
    const float* x  = (const float*)d_in[0];
    const float* wq = (const float*)d_in[1];
    const float* wk = (const float*)d_in[2];
    const float* wv = (const float*)d_in[3];
    const float* wo = (const float*)d_in[4];
    const float* bo = (const float*)d_in[5];
    float* out = (float*)d_out;

    k_qkv<<<dim3(NTOK / 64, INCDIM / 64), 256>>>(x, wq, wk, wv);
    k_integral<<<dim3(HW, HEADS), 256>>>();
    k_attn<<<dim3(HW, 3, HEADS), 256>>>();
    k_out<<<dim3(NTOK / 64, DIMX / 64), 256>>>(wo, bo, out);
}